// round 15
// baseline (speedup 1.0000x reference)
#include <cuda_runtime.h>
#include <cuda_fp16.h>

// ---------------------------------------------------------------------------
// Problem constants
// ---------------------------------------------------------------------------
#define BATCH 1024
#define DIN   512
#define DH    1024
#define DOUT  512
#define MHIST 6
#define MAXIT 40
#define LAM   1e-4f

#define SZ (BATCH * DH)

// ---------------------------------------------------------------------------
// Scratch (device globals: no runtime allocation allowed)
// ---------------------------------------------------------------------------
__device__ float g_X[MHIST * SZ];     // 24 MB
__device__ float g_F[MHIST * SZ];     // 24 MB
__device__ float g_z[SZ];
__device__ float g_P[2 * SZ];         // split-K partial sums (8 MB)
// fp16 activation operands (single term)
__device__ __half g_Af16[SZ];         // current z-like operand
__device__ __half g_Hf16[SZ];         // hidden activations
// fp16 weights W1,W2, transposed to [N,K] K-major
__device__ __half g_W1T[DH * DH];
__device__ __half g_W2T[DH * DH];

// ---------------------------------------------------------------------------
// Helpers
// ---------------------------------------------------------------------------
__device__ __forceinline__ unsigned smem_u32(const void* p) {
    unsigned r;
    asm("{ .reg .u64 t; cvta.to.shared.u64 t, %1; cvt.u32.u64 %0, t; }"
        : "=r"(r) : "l"(p));
    return r;
}

__device__ __forceinline__ unsigned pack_half2(float x, float y) {
    __half2 h = __floats2half2_rn(x, y);
    return *reinterpret_cast<unsigned*>(&h);
}

#define LDSM4(r, addr) \
    asm volatile("ldmatrix.sync.aligned.m8n8.x4.shared.b16 {%0,%1,%2,%3}, [%4];" \
        : "=r"((r)[0]), "=r"((r)[1]), "=r"((r)[2]), "=r"((r)[3]) : "r"(addr))
#define MMA_F16(d, a, b0, b1) \
    asm volatile("mma.sync.aligned.m16n8k16.row.col.f32.f16.f16.f32 " \
        "{%0,%1,%2,%3}, {%4,%5,%6,%7}, {%8,%9}, {%0,%1,%2,%3};" \
        : "+f"((d)[0]), "+f"((d)[1]), "+f"((d)[2]), "+f"((d)[3]) \
        : "r"((a)[0]), "r"((a)[1]), "r"((a)[2]), "r"((a)[3]), \
          "r"(b0), "r"(b1))

#define CP_ASYNC16(dst, src) \
    asm volatile("cp.async.cg.shared.global [%0], [%1], 16;" \
        :: "r"(dst), "l"(src) : "memory")
#define CP_COMMIT() asm volatile("cp.async.commit_group;" ::: "memory")
#define CP_WAIT2()  asm volatile("cp.async.wait_group 2;"  ::: "memory")

// ---------------------------------------------------------------------------
// Weight transpose to fp16: W[K,N] fp32 -> WT[N,K] fp16
// ---------------------------------------------------------------------------
__global__ void __launch_bounds__(256)
trans_kernel(const float* __restrict__ W, __half* __restrict__ WT)
{
    __shared__ float tile[32][33];
    const int tx = threadIdx.x & 31, ty = threadIdx.x >> 5;
    const int kb = blockIdx.y * 32, nb = blockIdx.x * 32;
#pragma unroll
    for (int r = 0; r < 4; ++r)
        tile[ty + r * 8][tx] = W[(size_t)(kb + ty + r * 8) * DH + nb + tx];
    __syncthreads();
#pragma unroll
    for (int r = 0; r < 4; ++r) {
        const int n = ty + r * 8;
        WT[(size_t)(nb + n) * DH + kb + tx] = __float2half_rn(tile[tx][n]);
    }
}

// ---------------------------------------------------------------------------
// Split-K fp16 GEMM:  P[z] = A * B over K-half z  (raw fp32 partials).
// A[M,K] K-major fp16 (activations), B[N,K] K-major fp16 (weights).
// CTA tile 128x64, KT=64, T=8 k-tiles per CTA (half of K=1024).
// grid (16, 8, 2): blockIdx.z = K-half. 2 CTAs co-resident per SM.
// 4-stage cp.async pipeline (96 KB smem); 8 warps 4(m) x 2(n), warp 32x32.
// ---------------------------------------------------------------------------
#define STAGE_B 24576
#define NSTAGES 4
#define SMEM_MMA (NSTAGES * STAGE_B)

__global__ void __launch_bounds__(256, 2)
gemm_sk(const __half* __restrict__ A,
        const __half* __restrict__ B)
{
    constexpr int K = 1024, LDC = 1024, KT = 64, T = 8;
    extern __shared__ char smem[];
    const unsigned sbase = smem_u32(smem);
    const int tid = threadIdx.x;
    const int lane = tid & 31, wid = tid >> 5;
    const int warp_m = wid >> 1, warp_n = wid & 1;   // 4(m) x 2(n)
    const int m0 = blockIdx.y * 128, n0 = blockIdx.x * 64;
    const int kbase = blockIdx.z * (T * KT);          // 0 or 512
    float* __restrict__ P = g_P + (size_t)blockIdx.z * SZ;

    float acc[2][4][4];
#pragma unroll
    for (int i = 0; i < 2; ++i)
#pragma unroll
        for (int j = 0; j < 4; ++j)
#pragma unroll
            for (int c = 0; c < 4; ++c) acc[i][j][c] = 0.f;

    // loader mapping: 256 threads, 16B granules; rows of 128B (64 fp16)
    const int lrow = tid >> 3;   // 0..31
    const int lc16 = tid & 7;    // 16B chunk within row

    auto load_stage = [&](int t, int s) {
        const int kt = kbase + t * KT;
        const unsigned stb = sbase + s * STAGE_B;
        const unsigned off0 = lrow * 128 + lc16 * 16;
        const unsigned sw0 = off0 ^ ((off0 >> 3) & 0x70);
#pragma unroll
        for (int it = 0; it < 4; ++it) {
            const size_t goff = (size_t)(m0 + it * 32 + lrow) * K + kt + lc16 * 8;
            CP_ASYNC16(stb + it * 4096 + sw0, A + goff);
        }
#pragma unroll
        for (int it = 0; it < 2; ++it) {
            const size_t goff = (size_t)(n0 + it * 32 + lrow) * K + kt + lc16 * 8;
            CP_ASYNC16(stb + 16384 + it * 4096 + sw0, B + goff);
        }
    };

    // per-thread ldmatrix offsets (warp tile 32x32)
    const int lr8 = lane & 7;
    const int lg  = (lane >> 3) & 1;
    const int lcg = lane >> 4;
    unsigned aoff[2];
#pragma unroll
    for (int i = 0; i < 2; ++i)
        aoff[i] = (unsigned)(warp_m * 32 + i * 16 + lr8 + lg * 8) * 128 + lcg * 16;
    unsigned boff[2];
#pragma unroll
    for (int jj = 0; jj < 2; ++jj)
        boff[jj] = (unsigned)(warp_n * 32 + jj * 16 + lr8 + lcg * 8) * 128 + lg * 16;

    // fragment buffers (double-buffered across k-steps)
    unsigned af[2][2][4], bf[2][2][4];

    auto ldfrag = [&](int buf, unsigned st, int ks) {
#pragma unroll
        for (int i = 0; i < 2; ++i) {
            unsigned off = aoff[i] + ks * 32;
            unsigned sw = off ^ ((off >> 3) & 0x70);
            LDSM4(af[buf][i], st + sw);
        }
#pragma unroll
        for (int jj = 0; jj < 2; ++jj) {
            unsigned off = boff[jj] + ks * 32;
            unsigned sw = off ^ ((off >> 3) & 0x70);
            LDSM4(bf[buf][jj], st + 16384 + sw);
        }
    };

    auto domma = [&](int buf) {
#pragma unroll
        for (int i = 0; i < 2; ++i)
#pragma unroll
            for (int j = 0; j < 4; ++j) {
                const int jj = j >> 1, p = (j & 1) * 2;
                MMA_F16(acc[i][j], af[buf][i], bf[buf][jj][p], bf[buf][jj][p + 1]);
            }
    };

    // ---- 4-stage cp.async mainloop over 8 k-tiles ----
#pragma unroll
    for (int s = 0; s < NSTAGES - 1; ++s) {
        load_stage(s, s);
        CP_COMMIT();
    }
    for (int t = 0; t < T; ++t) {
        CP_WAIT2();
        __syncthreads();
        if (t + NSTAGES - 1 < T)
            load_stage(t + NSTAGES - 1, (t + NSTAGES - 1) & (NSTAGES - 1));
        CP_COMMIT();
        const unsigned st = sbase + (t & (NSTAGES - 1)) * STAGE_B;
        ldfrag(0, st, 0);
#pragma unroll
        for (int ks = 0; ks < 4; ++ks) {
            const int cur = ks & 1;
            if (ks < 3) ldfrag(cur ^ 1, st, ks + 1);
            domma(cur);
        }
    }

    // ---- store raw partials ----
    const int erow = lane >> 2;
    const int ecol = (lane & 3) * 2;
#pragma unroll
    for (int i = 0; i < 2; ++i) {
        const int gm = m0 + warp_m * 32 + i * 16 + erow;
#pragma unroll
        for (int j = 0; j < 4; ++j) {
            const int gn = n0 + warp_n * 32 + j * 8 + ecol;
            const size_t o0 = (size_t)gm * LDC + gn;
            const size_t o1 = (size_t)(gm + 8) * LDC + gn;
            *reinterpret_cast<float2*>(P + o0) =
                make_float2(acc[i][j][0], acc[i][j][1]);
            *reinterpret_cast<float2*>(P + o1) =
                make_float2(acc[i][j][2], acc[i][j][3]);
        }
    }
}

// ---------------------------------------------------------------------------
// Split-K epilogue: v = P0 + P1 + bias (+relu); optional fp32 C, C2, fp16 S.
// One CTA per row, 256 threads x float4.
// ---------------------------------------------------------------------------
template <bool RELU>
__global__ void __launch_bounds__(256)
epi_kernel(const float* __restrict__ bias,
           float* __restrict__ C, float* __restrict__ C2,
           __half* __restrict__ S)
{
    const int row = blockIdx.x;
    const size_t base = (size_t)row * DH + threadIdx.x * 4;
    float4 p0 = *reinterpret_cast<const float4*>(g_P + base);
    float4 p1 = *reinterpret_cast<const float4*>(g_P + SZ + base);
    float4 b4 = *reinterpret_cast<const float4*>(bias + threadIdx.x * 4);
    float4 v;
    v.x = p0.x + p1.x + b4.x;
    v.y = p0.y + p1.y + b4.y;
    v.z = p0.z + p1.z + b4.z;
    v.w = p0.w + p1.w + b4.w;
    if (RELU) {
        v.x = fmaxf(v.x, 0.f); v.y = fmaxf(v.y, 0.f);
        v.z = fmaxf(v.z, 0.f); v.w = fmaxf(v.w, 0.f);
    }
    if (C)  *reinterpret_cast<float4*>(C + base) = v;
    if (C2) *reinterpret_cast<float4*>(C2 + base) = v;
    if (S) {
        uint2 sv;
        sv.x = pack_half2(v.x, v.y);
        sv.y = pack_half2(v.z, v.w);
        *reinterpret_cast<uint2*>(S + base) = sv;
    }
}

// ---------------------------------------------------------------------------
// FP32 SIMT GEMM (in/out projections), optional fp16 activation output
// ---------------------------------------------------------------------------
template <bool RELU>
__global__ void __launch_bounds__(256, 2)
gemm_kernel(const float* __restrict__ A, const float* __restrict__ B,
            const float* __restrict__ bias, float* __restrict__ C,
            __half* __restrict__ S, int N, int K)
{
    constexpr int BM = 128, BN = 64, BK = 16, TM = 8;
    __shared__ float As[BK][BM + 4];
    __shared__ float Bs[BK][BN];

    const int tid = threadIdx.x;
    const int tx  = tid & 15;
    const int ty  = tid >> 4;
    const int m0  = blockIdx.y * BM;
    const int n0  = blockIdx.x * BN;

    const int a_m0 = tid >> 2;
    const int a_m1 = a_m0 + 64;
    const int a_k4 = (tid & 3) * 4;
    const int b_kk = tid >> 4;
    const int b_n  = (tid & 15) * 4;

    unsigned long long acc[TM][2];
#pragma unroll
    for (int i = 0; i < TM; ++i) { acc[i][0] = 0ull; acc[i][1] = 0ull; }

    {
        float4 v0 = *reinterpret_cast<const float4*>(A + (size_t)(m0 + a_m0) * K + a_k4);
        float4 v1 = *reinterpret_cast<const float4*>(A + (size_t)(m0 + a_m1) * K + a_k4);
        As[a_k4 + 0][a_m0] = v0.x; As[a_k4 + 1][a_m0] = v0.y;
        As[a_k4 + 2][a_m0] = v0.z; As[a_k4 + 3][a_m0] = v0.w;
        As[a_k4 + 0][a_m1] = v1.x; As[a_k4 + 1][a_m1] = v1.y;
        As[a_k4 + 2][a_m1] = v1.z; As[a_k4 + 3][a_m1] = v1.w;
        float4 vb = *reinterpret_cast<const float4*>(B + (size_t)b_kk * N + n0 + b_n);
        *reinterpret_cast<float4*>(&Bs[b_kk][b_n]) = vb;
    }
    __syncthreads();

    const int ntiles = K / BK;
    for (int t = 0; t < ntiles; ++t) {
        float4 pa0, pa1, pb;
        const bool has_next = (t + 1 < ntiles);
        if (has_next) {
            const int k0 = (t + 1) * BK;
            pa0 = *reinterpret_cast<const float4*>(A + (size_t)(m0 + a_m0) * K + k0 + a_k4);
            pa1 = *reinterpret_cast<const float4*>(A + (size_t)(m0 + a_m1) * K + k0 + a_k4);
            pb  = *reinterpret_cast<const float4*>(B + (size_t)(k0 + b_kk) * N + n0 + b_n);
        }
#pragma unroll
        for (int kk = 0; kk < BK; ++kk) {
            float4 a0 = *reinterpret_cast<const float4*>(&As[kk][ty * TM]);
            float4 a1 = *reinterpret_cast<const float4*>(&As[kk][ty * TM + 4]);
            ulonglong2 bb = *reinterpret_cast<const ulonglong2*>(&Bs[kk][tx * 4]);
            float av[8] = {a0.x, a0.y, a0.z, a0.w, a1.x, a1.y, a1.z, a1.w};
#pragma unroll
            for (int i = 0; i < 8; ++i) {
                unsigned ai = __float_as_uint(av[i]);
                unsigned long long a2;
                asm("mov.b64 %0, {%1, %2};" : "=l"(a2) : "r"(ai), "r"(ai));
                asm("fma.rn.f32x2 %0, %1, %2, %3;"
                    : "=l"(acc[i][0]) : "l"(a2), "l"(bb.x), "l"(acc[i][0]));
                asm("fma.rn.f32x2 %0, %1, %2, %3;"
                    : "=l"(acc[i][1]) : "l"(a2), "l"(bb.y), "l"(acc[i][1]));
            }
        }
        __syncthreads();
        if (has_next) {
            As[a_k4 + 0][a_m0] = pa0.x; As[a_k4 + 1][a_m0] = pa0.y;
            As[a_k4 + 2][a_m0] = pa0.z; As[a_k4 + 3][a_m0] = pa0.w;
            As[a_k4 + 0][a_m1] = pa1.x; As[a_k4 + 1][a_m1] = pa1.y;
            As[a_k4 + 2][a_m1] = pa1.z; As[a_k4 + 3][a_m1] = pa1.w;
            *reinterpret_cast<float4*>(&Bs[b_kk][b_n]) = pb;
            __syncthreads();
        }
    }

    float4 bs4 = *reinterpret_cast<const float4*>(bias + n0 + tx * 4);
#pragma unroll
    for (int i = 0; i < TM; ++i) {
        unsigned l0, h0, l1, h1;
        asm("mov.b64 {%0, %1}, %2;" : "=r"(l0), "=r"(h0) : "l"(acc[i][0]));
        asm("mov.b64 {%0, %1}, %2;" : "=r"(l1), "=r"(h1) : "l"(acc[i][1]));
        float4 v;
        v.x = __uint_as_float(l0) + bs4.x;
        v.y = __uint_as_float(h0) + bs4.y;
        v.z = __uint_as_float(l1) + bs4.z;
        v.w = __uint_as_float(h1) + bs4.w;
        if (RELU) {
            v.x = fmaxf(v.x, 0.f); v.y = fmaxf(v.y, 0.f);
            v.z = fmaxf(v.z, 0.f); v.w = fmaxf(v.w, 0.f);
        }
        const size_t off = (size_t)(m0 + ty * TM + i) * N + n0 + tx * 4;
        *reinterpret_cast<float4*>(C + off) = v;
        if (S) {
            uint2 sv;
            sv.x = pack_half2(v.x, v.y);
            sv.y = pack_half2(v.z, v.w);
            *reinterpret_cast<uint2*>(S + off) = sv;
        }
    }
}

// ---------------------------------------------------------------------------
// Fused Anderson alpha + mix: one CTA per batch row.
// Writes xk to g_z (fp32), g_X[slot] (fp32), g_Af16 (fp16).
// ---------------------------------------------------------------------------
template <int NV>
__global__ void __launch_bounds__(256)
anderson_mix_kernel(int slot)
{
    constexpr int NP = NV * (NV + 1) / 2;
    const int row = blockIdx.x;
    const int tid = threadIdx.x;

    const float* xb = g_X + (size_t)row * DH;
    const float* fb = g_F + (size_t)row * DH;

    float s[NP];
#pragma unroll
    for (int p = 0; p < NP; ++p) s[p] = 0.f;

    for (int d = tid; d < DH; d += 256) {
        float g[NV];
#pragma unroll
        for (int j = 0; j < NV; ++j)
            g[j] = fb[(size_t)j * SZ + d] - xb[(size_t)j * SZ + d];
        int p = 0;
#pragma unroll
        for (int j = 0; j < NV; ++j)
#pragma unroll
            for (int l = j; l < NV; ++l) { s[p] += g[j] * g[l]; ++p; }
    }

#pragma unroll
    for (int p = 0; p < NP; ++p) {
        float v = s[p];
#pragma unroll
        for (int off = 16; off > 0; off >>= 1)
            v += __shfl_down_sync(0xffffffffu, v, off);
        s[p] = v;
    }
    __shared__ float red[NP][8];
    __shared__ float al[NV];
    const int lane = tid & 31, warp = tid >> 5;
    if (lane == 0) {
#pragma unroll
        for (int p = 0; p < NP; ++p) red[p][warp] = s[p];
    }
    __syncthreads();

    if (tid == 0) {
        float GGp[NP];
#pragma unroll
        for (int p = 0; p < NP; ++p) {
            float v = 0.f;
#pragma unroll
            for (int w = 0; w < 8; ++w) v += red[p][w];
            GGp[p] = v;
        }
        float GG[NV][NV];
        {
            int p = 0;
#pragma unroll
            for (int j = 0; j < NV; ++j)
#pragma unroll
                for (int l = j; l < NV; ++l) { GG[j][l] = GGp[p]; GG[l][j] = GGp[p]; ++p; }
        }
        const int n = NV + 1;
        float Hm[MHIST + 1][MHIST + 2];
        Hm[0][0] = 0.f;
        for (int j = 0; j < NV; ++j) { Hm[0][1 + j] = 1.f; Hm[1 + j][0] = 1.f; }
        for (int j = 0; j < NV; ++j)
            for (int l = 0; l < NV; ++l)
                Hm[1 + j][1 + l] = GG[j][l] + (j == l ? LAM : 0.f);
        for (int r = 0; r < n; ++r) Hm[r][n] = (r == 0) ? 1.f : 0.f;

        for (int c = 0; c < n; ++c) {
            int piv = c; float best = fabsf(Hm[c][c]);
            for (int r = c + 1; r < n; ++r) {
                float v = fabsf(Hm[r][c]);
                if (v > best) { best = v; piv = r; }
            }
            if (piv != c)
                for (int cc = 0; cc <= n; ++cc) {
                    float tmp = Hm[c][cc]; Hm[c][cc] = Hm[piv][cc]; Hm[piv][cc] = tmp;
                }
            float inv = 1.f / Hm[c][c];
            for (int r = c + 1; r < n; ++r) {
                float fct = Hm[r][c] * inv;
                for (int cc = c; cc <= n; ++cc) Hm[r][cc] -= fct * Hm[c][cc];
            }
        }
        float xv[MHIST + 1];
        for (int r = n - 1; r >= 0; --r) {
            float a = Hm[r][n];
            for (int cc = r + 1; cc < n; ++cc) a -= Hm[r][cc] * xv[cc];
            xv[r] = a / Hm[r][r];
        }
#pragma unroll
        for (int j = 0; j < NV; ++j) al[j] = xv[1 + j];
    }
    __syncthreads();

    // mix: xk = sum_j al[j] * F[j][row][:], 256 threads x float4
    const size_t base = (size_t)row * DH + tid * 4;
    float4 acc = make_float4(0.f, 0.f, 0.f, 0.f);
#pragma unroll
    for (int j = 0; j < NV; ++j) {
        const float a = al[j];
        float4 f = *reinterpret_cast<const float4*>(&g_F[(size_t)j * SZ + base]);
        acc.x += a * f.x; acc.y += a * f.y; acc.z += a * f.z; acc.w += a * f.w;
    }
    *reinterpret_cast<float4*>(&g_z[base]) = acc;
    *reinterpret_cast<float4*>(&g_X[(size_t)slot * SZ + base]) = acc;
    uint2 sv;
    sv.x = pack_half2(acc.x, acc.y);
    sv.y = pack_half2(acc.z, acc.w);
    *reinterpret_cast<uint2*>(g_Af16 + base) = sv;
}

// ---------------------------------------------------------------------------
// Host orchestration
// ---------------------------------------------------------------------------
static void launch_anderson_mix(int nv, int slot)
{
    switch (nv) {
        case 2: anderson_mix_kernel<2><<<BATCH, 256>>>(slot); break;
        case 3: anderson_mix_kernel<3><<<BATCH, 256>>>(slot); break;
        case 4: anderson_mix_kernel<4><<<BATCH, 256>>>(slot); break;
        case 5: anderson_mix_kernel<5><<<BATCH, 256>>>(slot); break;
        default: anderson_mix_kernel<6><<<BATCH, 256>>>(slot); break;
    }
}

extern "C" void kernel_launch(void* const* d_in, const int* in_sizes, int n_in,
                              void* d_out, int out_size)
{
    const float* x     = (const float*)d_in[0];
    const float* W_in  = (const float*)d_in[1];
    const float* b_in  = (const float*)d_in[2];
    const float* W1    = (const float*)d_in[3];
    const float* b1    = (const float*)d_in[4];
    const float* W2    = (const float*)d_in[5];
    const float* b2    = (const float*)d_in[6];
    const float* W_out = (const float*)d_in[7];
    const float* b_out = (const float*)d_in[8];
    float* out = (float*)d_out;

    float *X, *F, *z;
    __half *Af16, *Hf16, *W1T, *W2T;
    cudaGetSymbolAddress((void**)&X, g_X);
    cudaGetSymbolAddress((void**)&F, g_F);
    cudaGetSymbolAddress((void**)&z, g_z);
    cudaGetSymbolAddress((void**)&Af16, g_Af16);
    cudaGetSymbolAddress((void**)&Hf16, g_Hf16);
    cudaGetSymbolAddress((void**)&W1T, g_W1T);
    cudaGetSymbolAddress((void**)&W2T, g_W2T);

    cudaFuncSetAttribute(gemm_sk,
                         cudaFuncAttributeMaxDynamicSharedMemorySize, SMEM_MMA);

    // one-time weight transpose to fp16
    trans_kernel<<<dim3(32, 32), 256>>>(W1, W1T);
    trans_kernel<<<dim3(32, 32), 256>>>(W2, W2T);

    const dim3 skg(16, 8, 2);   // N/64, M/128, K-halves

    // z0 = x @ W_in + b_in -> X[0] fp32 + fp16 operand
    gemm_kernel<false><<<dim3(DH / 64, BATCH / 128), 256>>>(
        x, W_in, b_in, X, Af16, DH, DIN);

    // F0 = f(X0); X1 = F0 (dual store + fp16 operand)
    gemm_sk<<<skg, 256, SMEM_MMA>>>(Af16, W1T);
    epi_kernel<true ><<<BATCH, 256>>>(b1, nullptr, nullptr, Hf16);
    gemm_sk<<<skg, 256, SMEM_MMA>>>(Hf16, W2T);
    epi_kernel<false><<<BATCH, 256>>>(b2, F, X + SZ, Af16);
    // F1 = f(X1)
    gemm_sk<<<skg, 256, SMEM_MMA>>>(Af16, W1T);
    epi_kernel<true ><<<BATCH, 256>>>(b1, nullptr, nullptr, Hf16);
    gemm_sk<<<skg, 256, SMEM_MMA>>>(Hf16, W2T);
    epi_kernel<false><<<BATCH, 256>>>(b2, F + SZ, nullptr, nullptr);

    for (int k = 2; k < MAXIT; ++k) {
        const int nv   = (k < MHIST) ? k : MHIST;
        const int slot = k % MHIST;
        launch_anderson_mix(nv, slot);   // -> z, X[slot], Af16
        if (k < MAXIT - 1) {
            gemm_sk<<<skg, 256, SMEM_MMA>>>(Af16, W1T);
            epi_kernel<true ><<<BATCH, 256>>>(b1, nullptr, nullptr, Hf16);
            gemm_sk<<<skg, 256, SMEM_MMA>>>(Hf16, W2T);
            epi_kernel<false><<<BATCH, 256>>>(b2, F + (size_t)slot * SZ,
                                              nullptr, nullptr);
        }
    }

    // out = z_star @ W_out + b_out (exact fp32)
    gemm_kernel<false><<<dim3(DOUT / 64, BATCH / 128), 256>>>(
        z, W_out, b_out, out, nullptr, DOUT, DH);
}

// round 16
// speedup vs baseline: 1.1417x; 1.1417x over previous
#include <cuda_runtime.h>
#include <cuda_fp16.h>

// ---------------------------------------------------------------------------
// Problem constants
// ---------------------------------------------------------------------------
#define BATCH 1024
#define DIN   512
#define DH    1024
#define DOUT  512
#define MHIST 6
#define MAXIT 40
#define LAM   1e-4f

#define SZ (BATCH * DH)

// ---------------------------------------------------------------------------
// Scratch (device globals: no runtime allocation allowed)
// ---------------------------------------------------------------------------
__device__ float g_X[MHIST * SZ];     // 24 MB
__device__ float g_F[MHIST * SZ];     // 24 MB
__device__ float g_z[SZ];
// fp16 activation operands
__device__ __half g_xf16[BATCH * DIN];
__device__ __half g_Af16[SZ];         // current z-like operand
__device__ __half g_Hf16[SZ];         // hidden activations
// fp16 weights, transposed to [N,K] K-major
__device__ __half g_W1T[DH * DH];
__device__ __half g_W2T[DH * DH];
__device__ __half g_WinT[DIN * DH];   // [1024 N, 512 K]
__device__ __half g_WoutT[DH * DOUT]; // [512 N, 1024 K]

// ---------------------------------------------------------------------------
// Helpers
// ---------------------------------------------------------------------------
__device__ __forceinline__ unsigned smem_u32(const void* p) {
    unsigned r;
    asm("{ .reg .u64 t; cvta.to.shared.u64 t, %1; cvt.u32.u64 %0, t; }"
        : "=r"(r) : "l"(p));
    return r;
}

__device__ __forceinline__ unsigned pack_half2(float x, float y) {
    __half2 h = __floats2half2_rn(x, y);
    return *reinterpret_cast<unsigned*>(&h);
}

#define LDSM4(r, addr) \
    asm volatile("ldmatrix.sync.aligned.m8n8.x4.shared.b16 {%0,%1,%2,%3}, [%4];" \
        : "=r"((r)[0]), "=r"((r)[1]), "=r"((r)[2]), "=r"((r)[3]) : "r"(addr))
#define MMA_F16(d, a, b0, b1) \
    asm volatile("mma.sync.aligned.m16n8k16.row.col.f32.f16.f16.f32 " \
        "{%0,%1,%2,%3}, {%4,%5,%6,%7}, {%8,%9}, {%0,%1,%2,%3};" \
        : "+f"((d)[0]), "+f"((d)[1]), "+f"((d)[2]), "+f"((d)[3]) \
        : "r"((a)[0]), "r"((a)[1]), "r"((a)[2]), "r"((a)[3]), \
          "r"(b0), "r"(b1))

#define CP_ASYNC16(dst, src) \
    asm volatile("cp.async.cg.shared.global [%0], [%1], 16;" \
        :: "r"(dst), "l"(src) : "memory")
#define CP_COMMIT() asm volatile("cp.async.commit_group;" ::: "memory")
#define CP_WAIT2()  asm volatile("cp.async.wait_group 2;"  ::: "memory")

// ---------------------------------------------------------------------------
// Weight transpose to fp16: W[Kd,Nd] fp32 -> WT[Nd,Kd] fp16
// ---------------------------------------------------------------------------
__global__ void __launch_bounds__(256)
trans_kernel(const float* __restrict__ W, __half* __restrict__ WT,
             int Kd, int Nd)
{
    __shared__ float tile[32][33];
    const int tx = threadIdx.x & 31, ty = threadIdx.x >> 5;
    const int kb = blockIdx.y * 32, nb = blockIdx.x * 32;
#pragma unroll
    for (int r = 0; r < 4; ++r)
        tile[ty + r * 8][tx] = W[(size_t)(kb + ty + r * 8) * Nd + nb + tx];
    __syncthreads();
#pragma unroll
    for (int r = 0; r < 4; ++r) {
        const int n = ty + r * 8;
        WT[(size_t)(nb + n) * Kd + kb + tx] = __float2half_rn(tile[tx][n]);
    }
}

// fp32 -> fp16 convert (vectorized)
__global__ void __launch_bounds__(256)
tof16_kernel(const float* __restrict__ src, __half* __restrict__ dst)
{
    const size_t i = ((size_t)blockIdx.x * 256 + threadIdx.x) * 4;
    float4 v = *reinterpret_cast<const float4*>(src + i);
    uint2 o;
    o.x = pack_half2(v.x, v.y);
    o.y = pack_half2(v.z, v.w);
    *reinterpret_cast<uint2*>(dst + i) = o;
}

// ---------------------------------------------------------------------------
// fp16 GEMM with in-CTA k-split:  D = A*B, fp32 accum.
// A[M,K] K-major fp16, B[N,K] K-major fp16 (pre-transposed weights).
// CTA tile 128x64, KT=64; 8 warps as 2(m) x 2(n) x 2(k); warp tile 64x32.
// Each warp handles 2 of the 4 k-steps of every tile; final k-reduction
// through a 32 KB smem buffer, epilogue by the warp_k==0 warps.
// 4-stage cp.async pipeline (96 KB) + 32 KB reduce = 128 KB dynamic smem.
// ---------------------------------------------------------------------------
#define STAGE_B 24576
#define NSTAGES 4
#define SMEM_MMA (NSTAGES * STAGE_B + 32768)

template <bool RELU, int K, int N>
__global__ void __launch_bounds__(256, 1)
gemm_mma(const __half* __restrict__ A,
         const __half* __restrict__ B,
         const float* __restrict__ bias,
         float* __restrict__ C, float* __restrict__ C2,
         __half* __restrict__ S)
{
    constexpr int KT = 64, T = K / KT;
    extern __shared__ char smem[];
    const unsigned sbase = smem_u32(smem);
    float* const red = reinterpret_cast<float*>(smem + NSTAGES * STAGE_B);
    const int tid = threadIdx.x;
    const int lane = tid & 31, wid = tid >> 5;
    const int warp_m = wid >> 2;         // 0..1 (64-row half)
    const int warp_n = (wid >> 1) & 1;   // 0..1 (32-col half)
    const int warp_k = wid & 1;          // 0..1 (k-step half)
    const int m0 = blockIdx.y * 128, n0 = blockIdx.x * 64;

    float acc[4][4][4];   // [m16 frag][n8 frag][4]
#pragma unroll
    for (int i = 0; i < 4; ++i)
#pragma unroll
        for (int j = 0; j < 4; ++j)
#pragma unroll
            for (int c = 0; c < 4; ++c) acc[i][j][c] = 0.f;

    // loader mapping: 256 threads, 16B granules; rows of 128B (64 fp16)
    const int lrow = tid >> 3;   // 0..31
    const int lc16 = tid & 7;    // 16B chunk within row

    auto load_stage = [&](int t, int s) {
        const int kt = t * KT;
        const unsigned stb = sbase + s * STAGE_B;
        const unsigned off0 = lrow * 128 + lc16 * 16;
        const unsigned sw0 = off0 ^ ((off0 >> 3) & 0x70);
#pragma unroll
        for (int it = 0; it < 4; ++it) {
            const size_t goff = (size_t)(m0 + it * 32 + lrow) * K + kt + lc16 * 8;
            CP_ASYNC16(stb + it * 4096 + sw0, A + goff);
        }
#pragma unroll
        for (int it = 0; it < 2; ++it) {
            const size_t goff = (size_t)(n0 + it * 32 + lrow) * K + kt + lc16 * 8;
            CP_ASYNC16(stb + 16384 + it * 4096 + sw0, B + goff);
        }
    };

    // per-thread ldmatrix offsets (warp tile 64x32)
    const int lr8 = lane & 7;
    const int lg  = (lane >> 3) & 1;
    const int lcg = lane >> 4;
    unsigned aoff[4];
#pragma unroll
    for (int i = 0; i < 4; ++i)
        aoff[i] = (unsigned)(warp_m * 64 + i * 16 + lr8 + lg * 8) * 128 + lcg * 16;
    unsigned boff[2];
#pragma unroll
    for (int jj = 0; jj < 2; ++jj)
        boff[jj] = (unsigned)(warp_n * 32 + jj * 16 + lr8 + lcg * 8) * 128 + lg * 16;

    // fragments for this warp's two k-steps
    unsigned af0[4][4], bf0[2][4], af1[4][4], bf1[2][4];

    auto ldA = [&](unsigned (&af)[4][4], unsigned st, int ks) {
#pragma unroll
        for (int i = 0; i < 4; ++i) {
            unsigned off = aoff[i] + ks * 32;
            unsigned sw = off ^ ((off >> 3) & 0x70);
            LDSM4(af[i], st + sw);
        }
    };
    auto ldB = [&](unsigned (&bf)[2][4], unsigned st, int ks) {
#pragma unroll
        for (int jj = 0; jj < 2; ++jj) {
            unsigned off = boff[jj] + ks * 32;
            unsigned sw = off ^ ((off >> 3) & 0x70);
            LDSM4(bf[jj], st + 16384 + sw);
        }
    };
    auto domma = [&](unsigned (&af)[4][4], unsigned (&bf)[2][4]) {
#pragma unroll
        for (int i = 0; i < 4; ++i)
#pragma unroll
            for (int j = 0; j < 4; ++j) {
                const int jj = j >> 1, p = (j & 1) * 2;
                MMA_F16(acc[i][j], af[i], bf[jj][p], bf[jj][p + 1]);
            }
    };

    // ---- 4-stage cp.async mainloop ----
#pragma unroll
    for (int s = 0; s < NSTAGES - 1; ++s) {
        load_stage(s, s);
        CP_COMMIT();
    }
    const int ks_a = warp_k * 2, ks_b = ks_a + 1;
    for (int t = 0; t < T; ++t) {
        CP_WAIT2();
        __syncthreads();
        if (t + NSTAGES - 1 < T)
            load_stage(t + NSTAGES - 1, (t + NSTAGES - 1) & (NSTAGES - 1));
        CP_COMMIT();
        const unsigned st = sbase + (t & (NSTAGES - 1)) * STAGE_B;
        ldA(af0, st, ks_a); ldB(bf0, st, ks_a);
        ldA(af1, st, ks_b); ldB(bf1, st, ks_b);
        domma(af0, bf0);
        domma(af1, bf1);
    }

    // ---- k-reduction through smem (region disjoint from stage buffers) ----
    const int erow = lane >> 2;
    const int ecol = (lane & 3) * 2;
    if (warp_k == 1) {
#pragma unroll
        for (int i = 0; i < 4; ++i) {
            const int rr = warp_m * 64 + i * 16 + erow;
#pragma unroll
            for (int j = 0; j < 4; ++j) {
                const int rc = warp_n * 32 + j * 8 + ecol;
                *reinterpret_cast<float2*>(red + rr * 64 + rc) =
                    make_float2(acc[i][j][0], acc[i][j][1]);
                *reinterpret_cast<float2*>(red + (rr + 8) * 64 + rc) =
                    make_float2(acc[i][j][2], acc[i][j][3]);
            }
        }
    }
    __syncthreads();

    // ---- epilogue by warp_k==0 warps ----
    if (warp_k == 0) {
#pragma unroll
        for (int i = 0; i < 4; ++i) {
            const int rr = warp_m * 64 + i * 16 + erow;
            const int gm = m0 + rr;
#pragma unroll
            for (int j = 0; j < 4; ++j) {
                const int rc = warp_n * 32 + j * 8 + ecol;
                const int gn = n0 + rc;
                float2 r0 = *reinterpret_cast<float2*>(red + rr * 64 + rc);
                float2 r1 = *reinterpret_cast<float2*>(red + (rr + 8) * 64 + rc);
                float2 b2 = *reinterpret_cast<const float2*>(bias + gn);
                float2 v0, v1;
                v0.x = acc[i][j][0] + r0.x + b2.x;
                v0.y = acc[i][j][1] + r0.y + b2.y;
                v1.x = acc[i][j][2] + r1.x + b2.x;
                v1.y = acc[i][j][3] + r1.y + b2.y;
                if (RELU) {
                    v0.x = fmaxf(v0.x, 0.f); v0.y = fmaxf(v0.y, 0.f);
                    v1.x = fmaxf(v1.x, 0.f); v1.y = fmaxf(v1.y, 0.f);
                }
                const size_t o0 = (size_t)gm * N + gn;
                const size_t o1 = (size_t)(gm + 8) * N + gn;
                if (C) {
                    *reinterpret_cast<float2*>(C + o0) = v0;
                    *reinterpret_cast<float2*>(C + o1) = v1;
                }
                if (C2) {
                    *reinterpret_cast<float2*>(C2 + o0) = v0;
                    *reinterpret_cast<float2*>(C2 + o1) = v1;
                }
                if (S) {
                    *reinterpret_cast<unsigned*>(S + o0) = pack_half2(v0.x, v0.y);
                    *reinterpret_cast<unsigned*>(S + o1) = pack_half2(v1.x, v1.y);
                }
            }
        }
    }
}

// ---------------------------------------------------------------------------
// Fused Anderson alpha + mix: one CTA per batch row.
// Writes xk to g_z (fp32), g_X[slot] (fp32), g_Af16 (fp16).
// ---------------------------------------------------------------------------
template <int NV>
__global__ void __launch_bounds__(256)
anderson_mix_kernel(int slot)
{
    constexpr int NP = NV * (NV + 1) / 2;
    const int row = blockIdx.x;
    const int tid = threadIdx.x;

    const float* xb = g_X + (size_t)row * DH;
    const float* fb = g_F + (size_t)row * DH;

    float s[NP];
#pragma unroll
    for (int p = 0; p < NP; ++p) s[p] = 0.f;

    for (int d = tid; d < DH; d += 256) {
        float g[NV];
#pragma unroll
        for (int j = 0; j < NV; ++j)
            g[j] = fb[(size_t)j * SZ + d] - xb[(size_t)j * SZ + d];
        int p = 0;
#pragma unroll
        for (int j = 0; j < NV; ++j)
#pragma unroll
            for (int l = j; l < NV; ++l) { s[p] += g[j] * g[l]; ++p; }
    }

#pragma unroll
    for (int p = 0; p < NP; ++p) {
        float v = s[p];
#pragma unroll
        for (int off = 16; off > 0; off >>= 1)
            v += __shfl_down_sync(0xffffffffu, v, off);
        s[p] = v;
    }
    __shared__ float red[NP][8];
    __shared__ float al[NV];
    const int lane = tid & 31, warp = tid >> 5;
    if (lane == 0) {
#pragma unroll
        for (int p = 0; p < NP; ++p) red[p][warp] = s[p];
    }
    __syncthreads();

    if (tid == 0) {
        float GGp[NP];
#pragma unroll
        for (int p = 0; p < NP; ++p) {
            float v = 0.f;
#pragma unroll
            for (int w = 0; w < 8; ++w) v += red[p][w];
            GGp[p] = v;
        }
        float GG[NV][NV];
        {
            int p = 0;
#pragma unroll
            for (int j = 0; j < NV; ++j)
#pragma unroll
                for (int l = j; l < NV; ++l) { GG[j][l] = GGp[p]; GG[l][j] = GGp[p]; ++p; }
        }
        const int n = NV + 1;
        float Hm[MHIST + 1][MHIST + 2];
        Hm[0][0] = 0.f;
        for (int j = 0; j < NV; ++j) { Hm[0][1 + j] = 1.f; Hm[1 + j][0] = 1.f; }
        for (int j = 0; j < NV; ++j)
            for (int l = 0; l < NV; ++l)
                Hm[1 + j][1 + l] = GG[j][l] + (j == l ? LAM : 0.f);
        for (int r = 0; r < n; ++r) Hm[r][n] = (r == 0) ? 1.f : 0.f;

        for (int c = 0; c < n; ++c) {
            int piv = c; float best = fabsf(Hm[c][c]);
            for (int r = c + 1; r < n; ++r) {
                float v = fabsf(Hm[r][c]);
                if (v > best) { best = v; piv = r; }
            }
            if (piv != c)
                for (int cc = 0; cc <= n; ++cc) {
                    float tmp = Hm[c][cc]; Hm[c][cc] = Hm[piv][cc]; Hm[piv][cc] = tmp;
                }
            float inv = 1.f / Hm[c][c];
            for (int r = c + 1; r < n; ++r) {
                float fct = Hm[r][c] * inv;
                for (int cc = c; cc <= n; ++cc) Hm[r][cc] -= fct * Hm[c][cc];
            }
        }
        float xv[MHIST + 1];
        for (int r = n - 1; r >= 0; --r) {
            float a = Hm[r][n];
            for (int cc = r + 1; cc < n; ++cc) a -= Hm[r][cc] * xv[cc];
            xv[r] = a / Hm[r][r];
        }
#pragma unroll
        for (int j = 0; j < NV; ++j) al[j] = xv[1 + j];
    }
    __syncthreads();

    // mix: xk = sum_j al[j] * F[j][row][:], 256 threads x float4
    const size_t base = (size_t)row * DH + tid * 4;
    float4 acc = make_float4(0.f, 0.f, 0.f, 0.f);
#pragma unroll
    for (int j = 0; j < NV; ++j) {
        const float a = al[j];
        float4 f = *reinterpret_cast<const float4*>(&g_F[(size_t)j * SZ + base]);
        acc.x += a * f.x; acc.y += a * f.y; acc.z += a * f.z; acc.w += a * f.w;
    }
    *reinterpret_cast<float4*>(&g_z[base]) = acc;
    *reinterpret_cast<float4*>(&g_X[(size_t)slot * SZ + base]) = acc;
    uint2 sv;
    sv.x = pack_half2(acc.x, acc.y);
    sv.y = pack_half2(acc.z, acc.w);
    *reinterpret_cast<uint2*>(g_Af16 + base) = sv;
}

// ---------------------------------------------------------------------------
// Host orchestration
// ---------------------------------------------------------------------------
static void launch_anderson_mix(int nv, int slot)
{
    switch (nv) {
        case 2: anderson_mix_kernel<2><<<BATCH, 256>>>(slot); break;
        case 3: anderson_mix_kernel<3><<<BATCH, 256>>>(slot); break;
        case 4: anderson_mix_kernel<4><<<BATCH, 256>>>(slot); break;
        case 5: anderson_mix_kernel<5><<<BATCH, 256>>>(slot); break;
        default: anderson_mix_kernel<6><<<BATCH, 256>>>(slot); break;
    }
}

extern "C" void kernel_launch(void* const* d_in, const int* in_sizes, int n_in,
                              void* d_out, int out_size)
{
    const float* x     = (const float*)d_in[0];
    const float* W_in  = (const float*)d_in[1];
    const float* b_in  = (const float*)d_in[2];
    const float* W1    = (const float*)d_in[3];
    const float* b1    = (const float*)d_in[4];
    const float* W2    = (const float*)d_in[5];
    const float* b2    = (const float*)d_in[6];
    const float* W_out = (const float*)d_in[7];
    const float* b_out = (const float*)d_in[8];
    float* out = (float*)d_out;

    float *X, *F, *z;
    __half *xf16, *Af16, *Hf16, *W1T, *W2T, *WinT, *WoutT;
    cudaGetSymbolAddress((void**)&X, g_X);
    cudaGetSymbolAddress((void**)&F, g_F);
    cudaGetSymbolAddress((void**)&z, g_z);
    cudaGetSymbolAddress((void**)&xf16, g_xf16);
    cudaGetSymbolAddress((void**)&Af16, g_Af16);
    cudaGetSymbolAddress((void**)&Hf16, g_Hf16);
    cudaGetSymbolAddress((void**)&W1T, g_W1T);
    cudaGetSymbolAddress((void**)&W2T, g_W2T);
    cudaGetSymbolAddress((void**)&WinT, g_WinT);
    cudaGetSymbolAddress((void**)&WoutT, g_WoutT);

    cudaFuncSetAttribute(gemm_mma<true, 1024, 1024>,
                         cudaFuncAttributeMaxDynamicSharedMemorySize, SMEM_MMA);
    cudaFuncSetAttribute(gemm_mma<false, 1024, 1024>,
                         cudaFuncAttributeMaxDynamicSharedMemorySize, SMEM_MMA);
    cudaFuncSetAttribute(gemm_mma<false, 512, 1024>,
                         cudaFuncAttributeMaxDynamicSharedMemorySize, SMEM_MMA);
    cudaFuncSetAttribute(gemm_mma<false, 1024, 512>,
                         cudaFuncAttributeMaxDynamicSharedMemorySize, SMEM_MMA);

    // one-time weight transposes + input convert
    trans_kernel<<<dim3(32, 32), 256>>>(W1, W1T, DH, DH);
    trans_kernel<<<dim3(32, 32), 256>>>(W2, W2T, DH, DH);
    trans_kernel<<<dim3(32, 16), 256>>>(W_in, WinT, DIN, DH);     // [512,1024]
    trans_kernel<<<dim3(16, 32), 256>>>(W_out, WoutT, DH, DOUT);  // [1024,512]
    tof16_kernel<<<(BATCH * DIN) / 1024, 256>>>(x, xf16);

    const dim3 tcg(16, 8);   // N/64, M/128

    // z0 = x @ W_in + b_in -> X[0] fp32 + fp16 operand (fp16 path; z0 noise
    // only perturbs the initial condition, forgotten by the contraction)
    gemm_mma<false, 512, 1024><<<tcg, 256, SMEM_MMA>>>(
        xf16, WinT, b_in, X, nullptr, Af16);

    // F0 = f(X0); X1 = F0 (dual store + fp16 operand)
    gemm_mma<true, 1024, 1024><<<tcg, 256, SMEM_MMA>>>(
        Af16, W1T, b1, nullptr, nullptr, Hf16);
    gemm_mma<false, 1024, 1024><<<tcg, 256, SMEM_MMA>>>(
        Hf16, W2T, b2, F, X + SZ, Af16);
    // F1 = f(X1)
    gemm_mma<true, 1024, 1024><<<tcg, 256, SMEM_MMA>>>(
        Af16, W1T, b1, nullptr, nullptr, Hf16);
    gemm_mma<false, 1024, 1024><<<tcg, 256, SMEM_MMA>>>(
        Hf16, W2T, b2, F + SZ, nullptr, nullptr);

    for (int k = 2; k < MAXIT; ++k) {
        const int nv   = (k < MHIST) ? k : MHIST;
        const int slot = k % MHIST;
        launch_anderson_mix(nv, slot);   // -> z, X[slot], Af16
        if (k < MAXIT - 1) {
            gemm_mma<true, 1024, 1024><<<tcg, 256, SMEM_MMA>>>(
                Af16, W1T, b1, nullptr, nullptr, Hf16);
            gemm_mma<false, 1024, 1024><<<tcg, 256, SMEM_MMA>>>(
                Hf16, W2T, b2, F + (size_t)slot * SZ, nullptr, nullptr);
        }
    }

    // out = z_star @ W_out + b_out (fp16 MMA path, fp32 accumulate)
    gemm_mma<false, 1024, 512><<<dim3(8, 8), 256, SMEM_MMA>>>(
        Af16, WoutT, b_out, out, nullptr, nullptr);
}